// round 1
// baseline (speedup 1.0000x reference)
#include <cuda_runtime.h>

#define N_CIN   64
#define N_COUT  128
#define KOFF    8
#define TILE    256     // pairs per block
#define CHUNK   16      // pairs staged per __syncthreads round

// ---- scratch (no allocations allowed) ----
__device__ __align__(16) float g_sum[N_COUT];
__device__ __align__(16) float g_sumsq[N_COUT];
__device__ __align__(16) float g_scale[N_COUT];
__device__ __align__(16) float g_bias[N_COUT];

static __device__ __forceinline__ unsigned long long pack2(float lo, float hi) {
    unsigned long long r;
    asm("mov.b64 %0, {%1, %2};" : "=l"(r) : "f"(lo), "f"(hi));
    return r;
}
static __device__ __forceinline__ float hsum2(unsigned long long v) {
    float lo = __uint_as_float((unsigned)(v & 0xffffffffull));
    float hi = __uint_as_float((unsigned)(v >> 32));
    return lo + hi;
}
// packed fp32x2 FMA (Blackwell-only path; ptxas never emits this from C++)
#define FMA2(d, a, b, c) \
    asm("fma.rn.f32x2 %0, %1, %2, %3;" : "=l"(d) : "l"(a), "l"(b), "l"(c))

// ---------------------------------------------------------------------------
// Kernel 1: zero the accumulator (d_out) and the BN stats
// ---------------------------------------------------------------------------
__global__ void zero_kernel(float4* __restrict__ out4, int n4) {
    const float4 z = make_float4(0.f, 0.f, 0.f, 0.f);
    int stride = gridDim.x * blockDim.x;
    for (int i = blockIdx.x * blockDim.x + threadIdx.x; i < n4; i += stride)
        out4[i] = z;
    if (blockIdx.x == 0 && threadIdx.x < N_COUT) {
        g_sum[threadIdx.x]   = 0.f;
        g_sumsq[threadIdx.x] = 0.f;
    }
}

// ---------------------------------------------------------------------------
// Kernel 2: gather -> per-offset GEMM (f32x2 packed FMA) -> scatter-add
// Block = 128 threads, one output channel per thread.
// Weight column pairs (K-dim adjacent) live in 32 x 64-bit registers.
// ---------------------------------------------------------------------------
__global__ void __launch_bounds__(128) spconv_kernel(
    const float* __restrict__ features,
    const float* __restrict__ weight,
    const int*   __restrict__ in_idx,
    const int*   __restrict__ out_idx,
    float*       __restrict__ out,
    int P)
{
    __shared__ __align__(16) float s_feat[CHUNK][N_CIN];
    __shared__ int s_oidx[CHUNK];

    const int tid = threadIdx.x;          // output channel
    const int k = blockIdx.y;             // kernel offset
    const int tile_base = blockIdx.x * TILE;

    // Load this thread's weight column, packed as {W[2j][c], W[2j+1][c]}
    const float* Wk = weight + k * (N_CIN * N_COUT);
    unsigned long long w2[N_CIN / 2];
#pragma unroll
    for (int j = 0; j < N_CIN / 2; j++) {
        float a = Wk[(2 * j)     * N_COUT + tid];
        float b = Wk[(2 * j + 1) * N_COUT + tid];
        w2[j] = pack2(a, b);
    }

    const int* ii = in_idx  + k * P;
    const int* oi = out_idx + k * P;

    for (int c0 = 0; c0 < TILE; c0 += CHUNK) {
        __syncthreads();
        // Stage CHUNK gathered feature rows (float4-vectorized)
        for (int q = tid; q < CHUNK * (N_CIN / 4); q += 128) {
            int r = q >> 4, qq = q & 15;
            int p = tile_base + c0 + r;
            float4 v = make_float4(0.f, 0.f, 0.f, 0.f);
            if (p < P) {
                int src = ii[p];
                v = ((const float4*)features)[src * (N_CIN / 4) + qq];
            }
            ((float4*)s_feat[r])[qq] = v;
        }
        if (tid < CHUNK) {
            int p = tile_base + c0 + tid;
            s_oidx[tid] = (p < P) ? oi[p] : -1;
        }
        __syncthreads();

#pragma unroll 1
        for (int j = 0; j < CHUNK; j++) {
            int o = s_oidx[j];
            if (o < 0) break;
            const ulonglong2* frow = (const ulonglong2*)s_feat[j];
            unsigned long long a0 = 0ull, a1 = 0ull, a2 = 0ull, a3 = 0ull;
#pragma unroll
            for (int q = 0; q < 16; q += 2) {
                ulonglong2 f01 = frow[q];
                ulonglong2 f23 = frow[q + 1];
                FMA2(a0, w2[2 * q],     f01.x, a0);
                FMA2(a1, w2[2 * q + 1], f01.y, a1);
                FMA2(a2, w2[2 * q + 2], f23.x, a2);
                FMA2(a3, w2[2 * q + 3], f23.y, a3);
            }
            float contrib = (hsum2(a0) + hsum2(a1)) + (hsum2(a2) + hsum2(a3));
            atomicAdd(&out[o * N_COUT + tid], contrib);
        }
    }
}

// ---------------------------------------------------------------------------
// Kernel 3: per-channel sum / sumsq reduction over the accumulated output
// ---------------------------------------------------------------------------
__global__ void __launch_bounds__(256) bn_reduce(const float4* __restrict__ out4, int n4) {
    __shared__ float4 ssum[256];
    __shared__ float4 ssq[256];
    const int tid = threadIdx.x;
    float4 s = make_float4(0.f, 0.f, 0.f, 0.f);
    float4 q = make_float4(0.f, 0.f, 0.f, 0.f);
    int stride = gridDim.x * 256;   // multiple of 32 -> channel-quad stays fixed
    for (int i = blockIdx.x * 256 + tid; i < n4; i += stride) {
        float4 v = out4[i];
        s.x += v.x; s.y += v.y; s.z += v.z; s.w += v.w;
        q.x += v.x * v.x; q.y += v.y * v.y; q.z += v.z * v.z; q.w += v.w * v.w;
    }
    ssum[tid] = s; ssq[tid] = q;
    __syncthreads();
    for (int off = 128; off >= 32; off >>= 1) {
        if (tid < off) {
            float4 a = ssum[tid], b = ssum[tid + off];
            a.x += b.x; a.y += b.y; a.z += b.z; a.w += b.w;
            ssum[tid] = a;
            float4 c = ssq[tid], d = ssq[tid + off];
            c.x += d.x; c.y += d.y; c.z += d.z; c.w += d.w;
            ssq[tid] = c;
        }
        __syncthreads();
    }
    if (tid < 32) {  // quad `tid` -> channels 4*tid .. 4*tid+3
        float4 s4 = ssum[tid], q4 = ssq[tid];
        atomicAdd(&g_sum[4 * tid + 0], s4.x);
        atomicAdd(&g_sum[4 * tid + 1], s4.y);
        atomicAdd(&g_sum[4 * tid + 2], s4.z);
        atomicAdd(&g_sum[4 * tid + 3], s4.w);
        atomicAdd(&g_sumsq[4 * tid + 0], q4.x);
        atomicAdd(&g_sumsq[4 * tid + 1], q4.y);
        atomicAdd(&g_sumsq[4 * tid + 2], q4.z);
        atomicAdd(&g_sumsq[4 * tid + 3], q4.w);
    }
}

// ---------------------------------------------------------------------------
// Kernel 4: fold stats + gamma/beta into per-channel scale/bias
// ---------------------------------------------------------------------------
__global__ void bn_finalize(const float* __restrict__ gamma,
                            const float* __restrict__ beta, float inv_n) {
    int c = threadIdx.x;
    float mean = g_sum[c] * inv_n;
    float var  = fmaf(-mean, mean, g_sumsq[c] * inv_n);   // biased variance
    float s = gamma[c] * rsqrtf(var + 1e-5f);
    g_scale[c] = s;
    g_bias[c]  = fmaf(-mean, s, beta[c]);
}

// ---------------------------------------------------------------------------
// Kernel 5: y = relu(x * scale + bias), in place
// ---------------------------------------------------------------------------
__global__ void __launch_bounds__(256) bn_apply(float4* __restrict__ out4, int n4) {
    const int tid = threadIdx.x;
    const int quad = tid & 31;   // stride is a multiple of 32 -> fixed quad
    float4 sc = ((const float4*)g_scale)[quad];
    float4 bi = ((const float4*)g_bias)[quad];
    int stride = gridDim.x * blockDim.x;
    for (int i = blockIdx.x * blockDim.x + tid; i < n4; i += stride) {
        float4 v = out4[i];
        v.x = fmaxf(fmaf(v.x, sc.x, bi.x), 0.f);
        v.y = fmaxf(fmaf(v.y, sc.y, bi.y), 0.f);
        v.z = fmaxf(fmaf(v.z, sc.z, bi.z), 0.f);
        v.w = fmaxf(fmaf(v.w, sc.w, bi.w), 0.f);
        out4[i] = v;
    }
}

// ---------------------------------------------------------------------------
extern "C" void kernel_launch(void* const* d_in, const int* in_sizes, int n_in,
                              void* d_out, int out_size) {
    const float* features = (const float*)d_in[0];   // [N_IN, 64]
    const float* weight   = (const float*)d_in[1];   // [8, 64, 128]
    const float* gamma    = (const float*)d_in[2];   // [128]
    const float* beta     = (const float*)d_in[3];   // [128]
    const int*   in_idx   = (const int*)d_in[4];     // [8, P]
    const int*   out_idx  = (const int*)d_in[5];     // [8, P]
    float* out = (float*)d_out;                      // [n_out, 128]

    const int P = in_sizes[4] / KOFF;
    const int n_out = out_size / N_COUT;
    const int n4 = out_size / 4;

    zero_kernel<<<2048, 256>>>((float4*)out, n4);

    dim3 grid((P + TILE - 1) / TILE, KOFF);
    spconv_kernel<<<grid, 128>>>(features, weight, in_idx, out_idx, out, P);

    bn_reduce<<<512, 256>>>((const float4*)out, n4);
    bn_finalize<<<1, N_COUT>>>(gamma, beta, 1.0f / (float)n_out);
    bn_apply<<<2048, 256>>>((float4*)out, n4);
}